// round 1
// baseline (speedup 1.0000x reference)
#include <cuda_runtime.h>
#include <cstdint>

// 2D acoustic FDTD: 4 shots x 512 steps on 256x256, 5-pt Laplacian,
// point source, 128 receivers/shot.
//
// Persistent kernel: 128 CTAs (4 shots x 32 z-slabs of 8 rows). Fields live in
// shared memory (two 10x258 padded buffers, swapped each step). Only the 2
// boundary rows per slab are exchanged through L2 each step, synchronized by
// per-CTA MONOTONIC flags (release/acquire) -> no grid-wide barrier, no
// cross-launch reset, graph-capturable, allocation-free.

#define NS    4
#define NT    512
#define NZ    256
#define NX    256
#define NR    128
#define SLABS 32
#define RP    8          // rows per slab
#define S     258        // padded row stride (x: 0 pad | 1..256 | 257 pad)
#define NCTA  (NS * SLABS)

// boundary exchange: [cta][parity][0=top row,1=bottom row][x]
__device__ float g_bound[NCTA * 2 * 2 * NX];
// monotonic per-CTA step flags (never reset; +NT per launch)
__device__ int g_flag[NCTA];

__device__ __forceinline__ int ld_acq(const int* p) {
    int v;
    asm volatile("ld.global.acquire.gpu.b32 %0, [%1];" : "=r"(v) : "l"(p) : "memory");
    return v;
}
__device__ __forceinline__ void st_rel(int* p, int v) {
    asm volatile("st.global.release.gpu.b32 [%0], %1;" :: "l"(p), "r"(v) : "memory");
}

__global__ void __launch_bounds__(256, 1)
wave_kernel(const float* __restrict__ xin,   // (NS, NT)
            const float* __restrict__ vp,    // (NZ, NX)
            const int*   __restrict__ src_z, // (NS,)
            const int*   __restrict__ src_x, // (NS,)
            const int*   __restrict__ rec_z, // (NS, NR)
            const int*   __restrict__ rec_x, // (NS, NR)
            float*       __restrict__ out)   // (NS, NT, NR, 1)
{
    __shared__ float bufA[10 * S];
    __shared__ float bufB[10 * S];
    __shared__ int   rcnt;
    __shared__ int   rpos[NR];
    __shared__ short rid[NR];
    __shared__ int   sbase;

    const int tid = threadIdx.x;
    const int bid = blockIdx.x;
    const int s   = bid >> 5;      // shot
    const int b   = bid & 31;      // slab
    const int r0  = b * RP;        // first owned global row
    const int xi  = tid + 1;       // padded column index (global x = tid)

    // zero both buffers (halo rows/pad columns stay 0 unless rewritten)
    for (int i = tid; i < 10 * S; i += 256) { bufA[i] = 0.0f; bufB[i] = 0.0f; }
    if (tid == 0) { rcnt = 0; sbase = ld_acq(&g_flag[bid]); }
    __syncthreads();

    // build receiver list for this slab
    if (tid < NR) {
        int rz = rec_z[s * NR + tid];
        if (rz >= r0 && rz < r0 + RP) {
            int i = atomicAdd(&rcnt, 1);
            rpos[i] = (rz - r0 + 1) * S + rec_x[s * NR + tid] + 1;
            rid[i]  = (short)tid;
        }
    }

    const int  srcz    = src_z[s];
    const int  srcx    = src_x[s];
    const bool has_src = (srcz >= r0 && srcz < r0 + RP);
    const int  szl     = srcz - r0;

    // per-cell (vp*DT)^2 in registers
    float c2[RP];
#pragma unroll
    for (int z = 0; z < RP; z++) {
        float a = vp[(r0 + z) * NX + tid] * 0.001f;
        c2[z] = a * a;
    }
    __syncthreads();
    const int base = sbase;

    float* pcur = bufA;   // current field p_t   (rows 1..8 owned, 0/9 halo)
    float* pold = bufB;   // p_{t-1}; overwritten in place with p_{t+1}

    const float inv_dh2 = 1.0f / 100.0f;
    const bool  has_up  = (b > 0);
    const bool  has_dn  = (b < SLABS - 1);

    for (int t = 0; t < NT; t++) {
        if (t > 0) {
            const int tgt = base + t;
            if (tid == 0 && has_up) { while (ld_acq(&g_flag[bid - 1]) < tgt) {} }
            if (tid == 32 && has_dn) { while (ld_acq(&g_flag[bid + 1]) < tgt) {} }
            __syncthreads();
            const int par = t & 1;
            if (has_up)  // neighbor above's bottom row -> our top halo
                pcur[0 * S + xi] = __ldcg(&g_bound[(((bid - 1) * 2 + par) * 2 + 1) * NX + tid]);
            if (has_dn)  // neighbor below's top row -> our bottom halo
                pcur[9 * S + xi] = __ldcg(&g_bound[(((bid + 1) * 2 + par) * 2 + 0) * NX + tid]);
        }

        // publish base for p_{t+1} boundaries
        const int pb = (((bid * 2) + ((t + 1) & 1)) * 2) * NX;

        float srcval = 0.0f;
        if (has_src && tid == srcx)
            srcval = (__ldg(&xin[s * NT + t]) * 0.001f) * 0.001f;

        float pm = pcur[0 * S + xi];   // p[z-1]
        float pc = pcur[1 * S + xi];   // p[z]
#pragma unroll
        for (int z = 0; z < RP; z++) {
            float pn  = pcur[(z + 2) * S + xi];        // p[z+1]
            float l   = pcur[(z + 1) * S + xi - 1];
            float r   = pcur[(z + 1) * S + xi + 1];
            float old = pold[(z + 1) * S + xi];
            float lap = ((pm + pn) + (l + r) - 4.0f * pc) * inv_dh2;
            float val = 2.0f * pc - old + c2[z] * lap;
            if (has_src && z == szl && tid == srcx) val += srcval;
            pold[(z + 1) * S + xi] = val;              // p_{t+1} in place
            if (z == 0)      g_bound[pb + tid]      = val;  // top row
            if (z == RP - 1) g_bound[pb + NX + tid] = val;  // bottom row
            pm = pc; pc = pn;
        }

        __threadfence();        // boundary rows visible at GPU scope
        __syncthreads();        // all lanes' stores done before flag
        if (tid == 0) st_rel(&g_flag[bid], base + t + 1);

        // record receivers from the freshly-written p_{t+1} (in pold)
        for (int i = tid; i < rcnt; i += 256)
            out[(s * NT + t) * NR + rid[i]] = pold[rpos[i]];

        // swap: pold now holds p_{t+1}
        float* tmp = pcur; pcur = pold; pold = tmp;
    }
}

extern "C" void kernel_launch(void* const* d_in, const int* in_sizes, int n_in,
                              void* d_out, int out_size)
{
    const float* x     = (const float*)d_in[0];
    const float* vp    = (const float*)d_in[1];
    const int*   src_z = (const int*)d_in[2];
    const int*   src_x = (const int*)d_in[3];
    const int*   rec_z = (const int*)d_in[4];
    const int*   rec_x = (const int*)d_in[5];
    float*       out   = (float*)d_out;

    wave_kernel<<<NCTA, 256>>>(x, vp, src_z, src_x, rec_z, rec_x, out);
}

// round 2
// speedup vs baseline: 3.8704x; 3.8704x over previous
#include <cuda_runtime.h>
#include <cstdint>

// 2D acoustic FDTD, 4 shots x 512 steps, 256x256 grid.
// 4 clusters (one per shot) x 8 CTAs (32 rows each). Fields in smem
// (two 34x258 buffers, in-place leapfrog; p_{t-1} in registers).
// Halo rows pushed to neighbor CTAs via DSMEM (mapa + st.shared::cluster);
// one barrier.cluster per step. No global-memory sync, no persistent state.

#define NS    4
#define NT    512
#define NZ    256
#define NX    256
#define NR    128
#define CSZ   8            // CTAs per cluster (one cluster per shot)
#define RP    32           // rows per CTA
#define S     258          // padded row stride
#define ROWS  (RP + 2)     // 34 rows incl. halo
#define SMEMF (2 * ROWS * S)

__device__ __forceinline__ uint32_t smem_u32(const void* p) {
    uint32_t a;
    asm("{ .reg .u64 t; cvta.to.shared.u64 t, %1; cvt.u32.u64 %0, t; }"
        : "=r"(a) : "l"(p));
    return a;
}
__device__ __forceinline__ void st_dsmem(uint32_t laddr, uint32_t rank, float v) {
    uint32_t ra;
    asm volatile("mapa.shared::cluster.u32 %0, %1, %2;" : "=r"(ra) : "r"(laddr), "r"(rank));
    asm volatile("st.shared::cluster.f32 [%0], %1;" :: "r"(ra), "f"(v) : "memory");
}
__device__ __forceinline__ void cluster_sync() {
    asm volatile("barrier.cluster.arrive.aligned;" ::: "memory");
    asm volatile("barrier.cluster.wait.aligned;" ::: "memory");
}

__global__ void __launch_bounds__(256, 1) __cluster_dims__(CSZ, 1, 1)
wave_kernel(const float* __restrict__ xin,   // (NS, NT)
            const float* __restrict__ vp,    // (NZ, NX)
            const int*   __restrict__ src_z, // (NS,)
            const int*   __restrict__ src_x, // (NS,)
            const int*   __restrict__ rec_z, // (NS, NR)
            const int*   __restrict__ rec_x, // (NS, NR)
            float*       __restrict__ out)   // (NS, NT, NR, 1)
{
    extern __shared__ float smem[];          // [2][ROWS][S]
    __shared__ int   rcnt;
    __shared__ int   rpos[NR];
    __shared__ short rid[NR];

    const int tid  = threadIdx.x;
    const int bid  = blockIdx.x;
    const int s    = bid / CSZ;              // shot
    uint32_t rank;
    asm("mov.u32 %0, %%cluster_ctarank;" : "=r"(rank));
    const int r0   = (int)rank * RP;         // first owned global row
    const int xi   = tid + 1;                // padded column (global x = tid)

    // zero both buffers (halo rows / pad cols stay 0 unless pushed)
    for (int i = tid; i < SMEMF; i += 256) smem[i] = 0.0f;
    if (tid == 0) rcnt = 0;
    __syncthreads();

    // receiver list for this slab
    if (tid < NR) {
        int rz = rec_z[s * NR + tid];
        if (rz >= r0 && rz < r0 + RP) {
            int i = atomicAdd(&rcnt, 1);
            rpos[i] = (rz - r0 + 1) * S + rec_x[s * NR + tid] + 1;
            rid[i]  = (short)tid;
        }
    }

    const int  srcz    = src_z[s];
    const int  srcx    = src_x[s];
    const bool has_src = (srcz >= r0 && srcz < r0 + RP);
    const int  szl     = srcz - r0;          // 0..31 if has_src

    // c2h[z] = (vp*DT)^2 / DH^2 per owned cell
    float c2h[RP];
#pragma unroll
    for (int z = 0; z < RP; z++) {
        float a = vp[(r0 + z) * NX + tid] * 0.001f;
        c2h[z] = (a * a) * 0.01f;
    }

    // p_{t-1} in registers
    float pold[RP];
#pragma unroll
    for (int z = 0; z < RP; z++) pold[z] = 0.0f;

    __syncthreads();

    float* pcur = smem;                      // p_t
    float* pnxt = smem + ROWS * S;           // gets p_{t+1}
    const uint32_t nxt_base = smem_u32(smem + ROWS * S);
    const uint32_t cur_base = smem_u32(smem);

    const bool has_up = (rank > 0);
    const bool has_dn = (rank < CSZ - 1);

    for (int t = 0; t < NT; t++) {
        float srcval = 0.0f;
        if (has_src && tid == srcx)
            srcval = (__ldg(&xin[s * NT + t]) * 0.001f) * 0.001f;

        // DSMEM addresses of MY halo slots in the buffer being written;
        // same offsets in the neighbor's smem via mapa.
        const uint32_t nb = (t & 1) ? cur_base : nxt_base;   // buffer written this step
        const uint32_t up_slot = nb + (uint32_t)((ROWS - 1) * S + xi) * 4u; // row 33
        const uint32_t dn_slot = nb + (uint32_t)(0 * S + xi) * 4u;          // row 0

        float pm = pcur[0 * S + xi];
        float pc = pcur[1 * S + xi];
#pragma unroll
        for (int z = 0; z < RP; z++) {
            float pn  = pcur[(z + 2) * S + xi];
            float l   = pcur[(z + 1) * S + xi - 1];
            float r   = pcur[(z + 1) * S + xi + 1];
            float lap = (pm + pn) + (l + r) - 4.0f * pc;
            float val = 2.0f * pc - pold[z] + c2h[z] * lap;
            if (has_src && z == szl && tid == srcx) val += srcval;
            pold[z] = pc;
            pnxt[(z + 1) * S + xi] = val;
            if (z == 0      && has_up) st_dsmem(up_slot, rank - 1, val);
            if (z == RP - 1 && has_dn) st_dsmem(dn_slot, rank + 1, val);
            pm = pc; pc = pn;
        }

        __syncthreads();                     // local buffer complete

        // record receivers from freshly-written p_{t+1}
        for (int i = tid; i < rcnt; i += 256)
            out[(s * NT + t) * NR + rid[i]] = pnxt[rpos[i]];

        cluster_sync();                      // halo pushes visible cluster-wide

        float* tmp = pcur; pcur = pnxt; pnxt = tmp;
    }
}

extern "C" void kernel_launch(void* const* d_in, const int* in_sizes, int n_in,
                              void* d_out, int out_size)
{
    const float* x     = (const float*)d_in[0];
    const float* vp    = (const float*)d_in[1];
    const int*   src_z = (const int*)d_in[2];
    const int*   src_x = (const int*)d_in[3];
    const int*   rec_z = (const int*)d_in[4];
    const int*   rec_x = (const int*)d_in[5];
    float*       out   = (float*)d_out;

    cudaFuncSetAttribute(wave_kernel,
                         cudaFuncAttributeMaxDynamicSharedMemorySize,
                         SMEMF * (int)sizeof(float));
    wave_kernel<<<NS * CSZ, 256, SMEMF * (int)sizeof(float)>>>(
        x, vp, src_z, src_x, rec_z, rec_x, out);
}

// round 3
// speedup vs baseline: 6.9974x; 1.8079x over previous
#include <cuda_runtime.h>
#include <cstdint>

// 2D acoustic FDTD, 4 shots x 512 steps, 256x256 grid.
// One cluster per shot, CSZ CTAs x 256 threads; each thread owns one column
// of RP=NZ/CSZ rows, with p_t / p_{t-1} held in REGISTERS. A smem copy of
// p_t provides left/right neighbors (2 LDS + 1 STS per cell). Halo rows are
// pushed to neighbor CTAs via DSMEM; the cluster barrier is split
// (interior compute -> wait -> boundary rows + push -> arrive) so its
// latency hides under compute. CSZ=16 (nonportable) with CSZ=8 fallback.

#define NS    4
#define NT    512
#define NZ    256
#define NX    256
#define NR    128
#define S     258          // padded row stride

__device__ __forceinline__ uint32_t smem_u32(const void* p) {
    uint32_t a;
    asm("{ .reg .u64 t; cvta.to.shared.u64 t, %1; cvt.u32.u64 %0, t; }"
        : "=r"(a) : "l"(p));
    return a;
}
__device__ __forceinline__ void st_dsmem(uint32_t laddr, uint32_t rank, float v) {
    uint32_t ra;
    asm volatile("mapa.shared::cluster.u32 %0, %1, %2;" : "=r"(ra) : "r"(laddr), "r"(rank));
    asm volatile("st.shared::cluster.f32 [%0], %1;" :: "r"(ra), "f"(v) : "memory");
}
__device__ __forceinline__ void cluster_arrive() {
    asm volatile("barrier.cluster.arrive.aligned;" ::: "memory");
}
__device__ __forceinline__ void cluster_wait() {
    asm volatile("barrier.cluster.wait.aligned;" ::: "memory");
}

template<int CSZ>
__global__ void __launch_bounds__(256, 1) __cluster_dims__(CSZ, 1, 1)
wave_kernel(const float* __restrict__ xin,   // (NS, NT)
            const float* __restrict__ vp,    // (NZ, NX)
            const int*   __restrict__ src_z, // (NS,)
            const int*   __restrict__ src_x, // (NS,)
            const int*   __restrict__ rec_z, // (NS, NR)
            const int*   __restrict__ rec_x, // (NS, NR)
            float*       __restrict__ out)   // (NS, NT, NR, 1)
{
    constexpr int RP   = NZ / CSZ;      // rows per CTA
    constexpr int ROWS = RP + 2;        // + top/bottom halo rows
    extern __shared__ float smem[];     // [2][ROWS][S]
    __shared__ int   rcnt;
    __shared__ int   rpos[NR];
    __shared__ short rid[NR];

    const int tid = threadIdx.x;
    const int s   = blockIdx.x / CSZ;   // shot
    uint32_t rank;
    asm("mov.u32 %0, %%cluster_ctarank;" : "=r"(rank));
    const int r0 = (int)rank * RP;
    const int xi = tid + 1;

    for (int i = tid; i < 2 * ROWS * S; i += 256) smem[i] = 0.0f;
    if (tid == 0) rcnt = 0;
    __syncthreads();

    if (tid < NR) {
        int rz = rec_z[s * NR + tid];
        if (rz >= r0 && rz < r0 + RP) {
            int i = atomicAdd(&rcnt, 1);
            rpos[i] = (rz - r0 + 1) * S + rec_x[s * NR + tid] + 1;
            rid[i]  = (short)tid;
        }
    }

    const int  srcz    = src_z[s];
    const int  srcx    = src_x[s];
    const bool has_src = (srcz >= r0 && srcz < r0 + RP) && false; // replaced below
    (void)has_src;
    const bool my_src  = (srcz >= r0 && srcz < r0 + RP) && (tid == srcx);
    const int  szl     = srcz - r0;

    float c2h[RP], ccur[RP], cold[RP];
#pragma unroll
    for (int z = 0; z < RP; z++) {
        float a = vp[(r0 + z) * NX + tid] * 0.001f;
        c2h[z] = (a * a) * 0.01f;
        ccur[z] = 0.0f;
        cold[z] = 0.0f;
    }
    __syncthreads();

    float* b0 = smem;
    float* b1 = smem + ROWS * S;
    const uint32_t base0 = smem_u32(b0);
    const uint32_t base1 = smem_u32(b1);
    const bool has_up = (rank > 0);
    const bool has_dn = (rank < CSZ - 1);

    for (int t = 0; t < NT; t++) {
        float* pcur = (t & 1) ? b1 : b0;        // holds p_t (smem mirror)
        float* pnxt = (t & 1) ? b0 : b1;        // receives p_{t+1}
        const uint32_t nbase = (t & 1) ? base0 : base1;

        float srcval = 0.0f;
        if (my_src) srcval = (__ldg(&xin[s * NT + t]) * 0.001f) * 0.001f;

        // old boundary-adjacent values needed later by z=0 / z=RP-1
        const float save1 = ccur[1];
        const float saveB = ccur[RP - 2];

        // ---- interior rows z = 1 .. RP-2 (no halo dependency) ----
        float below = ccur[0];
#pragma unroll
        for (int z = 1; z <= RP - 2; z++) {
            float cz    = ccur[z];
            float above = ccur[z + 1];
            float l = pcur[(z + 1) * S + xi - 1];
            float r = pcur[(z + 1) * S + xi + 1];
            float val = 2.0f * cz - cold[z]
                      + c2h[z] * ((below + above) + (l + r) - 4.0f * cz);
            if (my_src && z == szl) val += srcval;
            cold[z] = cz; ccur[z] = val;
            pnxt[(z + 1) * S + xi] = val;
            below = cz;
        }

        // ---- wait for neighbors' halo pushes of p_t ----
        if (t > 0) cluster_wait();

        const float haloT = pcur[0 * S + xi];
        const float haloB = pcur[(ROWS - 1) * S + xi];

        // ---- z = 0 ----
        {
            float cz = ccur[0];
            float l = pcur[1 * S + xi - 1];
            float r = pcur[1 * S + xi + 1];
            float val = 2.0f * cz - cold[0]
                      + c2h[0] * ((haloT + save1) + (l + r) - 4.0f * cz);
            if (my_src && szl == 0) val += srcval;
            cold[0] = cz; ccur[0] = val;
            pnxt[1 * S + xi] = val;
            if (has_up)
                st_dsmem(nbase + (uint32_t)((ROWS - 1) * S + xi) * 4u, rank - 1, val);
        }
        // ---- z = RP-1 ----
        {
            float cz = ccur[RP - 1];
            float l = pcur[RP * S + xi - 1];
            float r = pcur[RP * S + xi + 1];
            float val = 2.0f * cz - cold[RP - 1]
                      + c2h[RP - 1] * ((saveB + haloB) + (l + r) - 4.0f * cz);
            if (my_src && szl == RP - 1) val += srcval;
            cold[RP - 1] = cz; ccur[RP - 1] = val;
            pnxt[RP * S + xi] = val;
            if (has_dn)
                st_dsmem(nbase + (uint32_t)(0 * S + xi) * 4u, rank + 1, val);
        }

        cluster_arrive();        // releases this CTA's pushes for phase t+1
        __syncthreads();         // local pnxt complete for receiver reads

        for (int i = tid; i < rcnt; i += 256)
            out[(s * NT + t) * NR + rid[i]] = pnxt[rpos[i]];
    }
    cluster_wait();              // balance final arrive; keep smem alive for
                                 // in-flight neighbor pushes before exit
}

extern "C" void kernel_launch(void* const* d_in, const int* in_sizes, int n_in,
                              void* d_out, int out_size)
{
    const float* x     = (const float*)d_in[0];
    const float* vp    = (const float*)d_in[1];
    const int*   src_z = (const int*)d_in[2];
    const int*   src_x = (const int*)d_in[3];
    const int*   rec_z = (const int*)d_in[4];
    const int*   rec_x = (const int*)d_in[5];
    float*       out   = (float*)d_out;

    const int smem16 = 2 * (NZ / 16 + 2) * S * (int)sizeof(float);
    const int smem8  = 2 * (NZ / 8  + 2) * S * (int)sizeof(float);

    // Try CSZ=16 (nonportable cluster size), validated via occupancy query.
    bool use16 = false;
    if (cudaFuncSetAttribute(wave_kernel<16>,
            cudaFuncAttributeNonPortableClusterSizeAllowed, 1) == cudaSuccess &&
        cudaFuncSetAttribute(wave_kernel<16>,
            cudaFuncAttributeMaxDynamicSharedMemorySize, smem16) == cudaSuccess) {
        cudaLaunchConfig_t cfg = {};
        cfg.gridDim  = dim3(NS * 16, 1, 1);
        cfg.blockDim = dim3(256, 1, 1);
        cfg.dynamicSmemBytes = (size_t)smem16;
        cudaLaunchAttribute attr[1];
        attr[0].id = cudaLaunchAttributeClusterDimension;
        attr[0].val.clusterDim = {16, 1, 1};
        cfg.attrs = attr;
        cfg.numAttrs = 1;
        int ncl = 0;
        cudaError_t e = cudaOccupancyMaxActiveClusters(&ncl, wave_kernel<16>, &cfg);
        if (e == cudaSuccess && ncl >= NS) use16 = true;
        else cudaGetLastError();   // clear any sticky error from the probe
    } else {
        cudaGetLastError();
    }

    if (use16) {
        wave_kernel<16><<<NS * 16, 256, smem16>>>(x, vp, src_z, src_x, rec_z, rec_x, out);
    } else {
        cudaFuncSetAttribute(wave_kernel<8>,
            cudaFuncAttributeMaxDynamicSharedMemorySize, smem8);
        wave_kernel<8><<<NS * 8, 256, smem8>>>(x, vp, src_z, src_x, rec_z, rec_x, out);
    }
}

// round 4
// speedup vs baseline: 8.6360x; 1.2342x over previous
#include <cuda_runtime.h>
#include <cstdint>

// 2D acoustic FDTD, 4 shots x 512 steps, 256x256 grid.
// One cluster per shot, CSZ CTAs x 512 threads. Each CTA owns RPC=NZ/CSZ rows,
// split into 2 thread-groups of RPT rows; p_t / p_{t-1} columns in registers,
// smem mirror provides left/right + seam + halo. Halo rows are pushed to
// neighbor CTAs with st.async (data + mbarrier tx-completion in one op);
// per-direction parity-indexed mbarriers replace the full cluster barrier.

#define NS    4
#define NT    512
#define NZ    256
#define NX    256
#define NR    128
#define S     258          // padded row stride

__device__ __forceinline__ uint32_t smem_u32(const void* p) {
    uint32_t a;
    asm("{ .reg .u64 t; cvta.to.shared.u64 t, %1; cvt.u32.u64 %0, t; }"
        : "=r"(a) : "l"(p));
    return a;
}
__device__ __forceinline__ uint32_t mapa32(uint32_t laddr, uint32_t rank) {
    uint32_t ra;
    asm("mapa.shared::cluster.u32 %0, %1, %2;" : "=r"(ra) : "r"(laddr), "r"(rank));
    return ra;
}
__device__ __forceinline__ void mbar_init(uint32_t mbar, uint32_t cnt) {
    asm volatile("mbarrier.init.shared::cta.b64 [%0], %1;" :: "r"(mbar), "r"(cnt) : "memory");
}
__device__ __forceinline__ void mbar_expect(uint32_t mbar, uint32_t tx) {
    asm volatile("mbarrier.arrive.expect_tx.shared::cta.b64 _, [%0], %1;"
                 :: "r"(mbar), "r"(tx) : "memory");
}
__device__ __forceinline__ void mbar_wait(uint32_t mbar, uint32_t parity) {
    asm volatile(
        "{\n\t"
        ".reg .pred P;\n\t"
        "LW%=:\n\t"
        "mbarrier.try_wait.parity.acquire.cluster.shared::cta.b64 P, [%0], %1;\n\t"
        "@P bra LD%=;\n\t"
        "bra LW%=;\n\t"
        "LD%=:\n\t"
        "}"
        :: "r"(mbar), "r"(parity) : "memory");
}
__device__ __forceinline__ void st_async_f32(uint32_t rslot, uint32_t rmbar, float v) {
    asm volatile("st.async.shared::cluster.mbarrier::complete_tx::bytes.b32 [%0], %1, [%2];"
                 :: "r"(rslot), "r"(__float_as_uint(v)), "r"(rmbar) : "memory");
}
__device__ __forceinline__ void cluster_sync_() {
    asm volatile("barrier.cluster.arrive.aligned;" ::: "memory");
    asm volatile("barrier.cluster.wait.aligned;" ::: "memory");
}

template<int CSZ>
__global__ void __launch_bounds__(512, 1) __cluster_dims__(CSZ, 1, 1)
wave_kernel(const float* __restrict__ xin,   // (NS, NT)
            const float* __restrict__ vp,    // (NZ, NX)
            const int*   __restrict__ src_z, // (NS,)
            const int*   __restrict__ src_x, // (NS,)
            const int*   __restrict__ rec_z, // (NS, NR)
            const int*   __restrict__ rec_x, // (NS, NR)
            float*       __restrict__ out)   // (NS, NT, NR, 1)
{
    constexpr int RPC  = NZ / CSZ;      // rows per CTA
    constexpr int RPT  = RPC / 2;       // rows per thread group
    constexpr int ROWS = RPC + 2;       // + halo rows 0 and ROWS-1
    extern __shared__ float smem[];     // [2][ROWS][S]
    // mbars[0/1] = top dir (recv from up), parity 0/1; [2/3] = bottom dir.
    __shared__ __align__(8) uint64_t mbars[4];
    __shared__ int   rcnt;
    __shared__ int   rpos[NR];
    __shared__ short rid[NR];

    const int tid = threadIdx.x;
    const int tyg = tid >> 8;           // thread group 0 (top half) / 1 (bottom)
    const int x   = tid & 255;
    const int xi  = x + 1;
    const int s   = blockIdx.x / CSZ;   // shot
    uint32_t rank;
    asm("mov.u32 %0, %%cluster_ctarank;" : "=r"(rank));
    const int r0  = (int)rank * RPC;    // first owned global row of CTA
    const int gz0 = tyg * RPT;          // first CTA-local row of this group

    for (int i = tid; i < 2 * ROWS * S; i += 512) smem[i] = 0.0f;
    if (tid == 0) {
        rcnt = 0;
        for (int i = 0; i < 4; i++) mbar_init(smem_u32(&mbars[i]), 1);
    }
    __syncthreads();
    cluster_sync_();                    // mbars initialized cluster-wide

    if (tid < NR) {
        int rz = rec_z[s * NR + tid];
        if (rz >= r0 && rz < r0 + RPC) {
            int i = atomicAdd(&rcnt, 1);
            rpos[i] = (rz - r0 + 1) * S + rec_x[s * NR + tid] + 1;
            rid[i]  = (short)tid;
        }
    }

    const int  srcz   = src_z[s];
    const int  srcx   = src_x[s];
    const int  szc    = srcz - r0;                 // CTA-local source row
    const bool my_src = (szc >= gz0 && szc < gz0 + RPT) && (x == srcx);
    const int  szl    = szc - gz0;                 // group-local source row

    float c2h[RPT], ccur[RPT], cold[RPT];
#pragma unroll
    for (int z = 0; z < RPT; z++) {
        float a = vp[(r0 + gz0 + z) * NX + x] * 0.001f;
        c2h[z] = (a * a) * 0.01f;
        ccur[z] = 0.0f;
        cold[z] = 0.0f;
    }
    __syncthreads();

    float* b0 = smem;
    float* b1 = smem + ROWS * S;
    const uint32_t base[2] = { smem_u32(b0), smem_u32(b1) };
    const uint32_t mb_top[2] = { smem_u32(&mbars[0]), smem_u32(&mbars[1]) };
    const uint32_t mb_bot[2] = { smem_u32(&mbars[2]), smem_u32(&mbars[3]) };
    const bool has_up = (rank > 0);
    const bool has_dn = (rank < CSZ - 1);

    for (int t = 0; t < NT; t++) {
        const int par = t & 1;
        float* pcur = par ? b1 : b0;                // p_t
        float* pnxt = par ? b0 : b1;                // receives p_{t+1}
        const uint32_t rbase = base[par ^ 1];       // remote buffer being written

        if (tid == 0) {                             // expect_tx for phase t
            if (has_up) mbar_expect(mb_top[par], NX * 4);
            if (has_dn) mbar_expect(mb_bot[par], NX * 4);
        }

        float srcval = 0.0f;
        if (my_src) srcval = (__ldg(&xin[s * NT + t]) * 0.001f) * 0.001f;

        if (tyg == 0) {
            const float save1 = ccur[1];            // old row-1 value for z=0
            float below = ccur[0];
#pragma unroll
            for (int z = 1; z < RPT; z++) {         // rows gz = 1..RPT-1
                float cz = ccur[z];
                float above = (z == RPT - 1) ? pcur[(RPT + 1) * S + xi]  // seam
                                             : ccur[z + 1];
                float l = pcur[(z + 1) * S + xi - 1];
                float r = pcur[(z + 1) * S + xi + 1];
                float val = 2.0f * cz - cold[z]
                          + c2h[z] * ((below + above) + (l + r) - 4.0f * cz);
                if (my_src && z == szl) val += srcval;
                cold[z] = cz; ccur[z] = val;
                pnxt[(z + 1) * S + xi] = val;
                below = cz;
            }
            // wait for up-neighbor's phase t-1 push (top halo of p_t)
            if (has_up && t > 0) mbar_wait(mb_top[(t - 1) & 1], ((t - 1) >> 1) & 1);
            {   // row gz = 0
                float cz = ccur[0];
                float haloT = pcur[0 * S + xi];
                float l = pcur[1 * S + xi - 1];
                float r = pcur[1 * S + xi + 1];
                float val = 2.0f * cz - cold[0]
                          + c2h[0] * ((haloT + save1) + (l + r) - 4.0f * cz);
                if (my_src && szl == 0) val += srcval;
                cold[0] = cz; ccur[0] = val;
                pnxt[1 * S + xi] = val;
                if (has_up) {   // -> up neighbor's bottom halo + its bot mbar
                    uint32_t rs = mapa32(rbase + (uint32_t)((ROWS - 1) * S + xi) * 4u, rank - 1);
                    uint32_t rm = mapa32(mb_bot[par], rank - 1);
                    st_async_f32(rs, rm, val);
                }
            }
        } else {
            float below = pcur[RPT * S + xi];       // seam: old row RPT-1
#pragma unroll
            for (int z = 0; z < RPT - 1; z++) {     // rows gz = RPT..RPC-2
                float cz = ccur[z];
                float above = ccur[z + 1];
                const int row = RPT + z + 1;        // smem row of gz
                float l = pcur[row * S + xi - 1];
                float r = pcur[row * S + xi + 1];
                float val = 2.0f * cz - cold[z]
                          + c2h[z] * ((below + above) + (l + r) - 4.0f * cz);
                if (my_src && z == szl) val += srcval;
                cold[z] = cz; ccur[z] = val;
                pnxt[row * S + xi] = val;
                below = cz;
            }
            // wait for down-neighbor's phase t-1 push (bottom halo of p_t)
            if (has_dn && t > 0) mbar_wait(mb_bot[(t - 1) & 1], ((t - 1) >> 1) & 1);
            {   // row gz = RPC-1
                constexpr int z = RPT - 1;
                float cz = ccur[z];
                float haloB = pcur[(ROWS - 1) * S + xi];
                float l = pcur[(RPC)*S + xi - 1];
                float r = pcur[(RPC)*S + xi + 1];
                float val = 2.0f * cz - cold[z]
                          + c2h[z] * ((below + haloB) + (l + r) - 4.0f * cz);
                if (my_src && z == szl) val += srcval;
                cold[z] = cz; ccur[z] = val;
                pnxt[(RPC)*S + xi] = val;
                if (has_dn) {   // -> down neighbor's top halo + its top mbar
                    uint32_t rs = mapa32(rbase + (uint32_t)(0 * S + xi) * 4u, rank + 1);
                    uint32_t rm = mapa32(mb_top[par], rank + 1);
                    st_async_f32(rs, rm, val);
                }
            }
        }

        __syncthreads();                            // pnxt complete locally

        for (int i = tid; i < rcnt; i += 512)
            out[(s * NT + t) * NR + rid[i]] = pnxt[rpos[i]];
    }

    // drain final phase (NT-1) so no st.async targets our smem after exit
    if (tid == 0) {
        const uint32_t fp = (NT - 1) & 1, fpar = ((NT - 1) >> 1) & 1;
        if (has_up) mbar_wait(mb_top[fp], fpar);
        if (has_dn) mbar_wait(mb_bot[fp], fpar);
    }
    __syncthreads();
    cluster_sync_();
}

template<int CSZ>
static void launch_variant(const float* x, const float* vp, const int* sz,
                           const int* sx, const int* rz, const int* rx, float* out)
{
    const int smemb = 2 * (NZ / CSZ + 2) * S * (int)sizeof(float);
    cudaFuncSetAttribute(wave_kernel<CSZ>,
                         cudaFuncAttributeMaxDynamicSharedMemorySize, smemb);
    wave_kernel<CSZ><<<NS * CSZ, 512, smemb>>>(x, vp, sz, sx, rz, rx, out);
}

extern "C" void kernel_launch(void* const* d_in, const int* in_sizes, int n_in,
                              void* d_out, int out_size)
{
    const float* x     = (const float*)d_in[0];
    const float* vp    = (const float*)d_in[1];
    const int*   src_z = (const int*)d_in[2];
    const int*   src_x = (const int*)d_in[3];
    const int*   rec_z = (const int*)d_in[4];
    const int*   rec_x = (const int*)d_in[5];
    float*       out   = (float*)d_out;

    const int smem16 = 2 * (NZ / 16 + 2) * S * (int)sizeof(float);
    bool use16 = false;
    if (cudaFuncSetAttribute(wave_kernel<16>,
            cudaFuncAttributeNonPortableClusterSizeAllowed, 1) == cudaSuccess &&
        cudaFuncSetAttribute(wave_kernel<16>,
            cudaFuncAttributeMaxDynamicSharedMemorySize, smem16) == cudaSuccess) {
        cudaLaunchConfig_t cfg = {};
        cfg.gridDim  = dim3(NS * 16, 1, 1);
        cfg.blockDim = dim3(512, 1, 1);
        cfg.dynamicSmemBytes = (size_t)smem16;
        cudaLaunchAttribute attr[1];
        attr[0].id = cudaLaunchAttributeClusterDimension;
        attr[0].val.clusterDim = {16, 1, 1};
        cfg.attrs = attr;
        cfg.numAttrs = 1;
        int ncl = 0;
        if (cudaOccupancyMaxActiveClusters(&ncl, wave_kernel<16>, &cfg) == cudaSuccess
            && ncl >= NS) use16 = true;
        else cudaGetLastError();
    } else {
        cudaGetLastError();
    }

    if (use16) launch_variant<16>(x, vp, src_z, src_x, rec_z, rec_x, out);
    else       launch_variant<8
    >(x, vp, src_z, src_x, rec_z, rec_x, out);
}

// round 5
// speedup vs baseline: 9.5446x; 1.1052x over previous
#include <cuda_runtime.h>
#include <cstdint>

// 2D acoustic FDTD, 4 shots x 512 steps, 256x256 grid.
// One cluster per shot, CSZ CTAs x 1024 threads (4 row-groups of RPT rows per
// thread). p_t / p_{t-1} columns in registers; smem mirror gives left/right +
// seams + halos. l/r preloaded in a batch (MLP=8) before compute. Halo rows
// pushed to neighbor CTAs with st.async + parity-indexed mbarriers.

#define NS    4
#define NT    512
#define NZ    256
#define NX    256
#define NR    128
#define S     258          // padded row stride
#define NG    4            // row groups per CTA (1024 threads / 256 cols)

__device__ __forceinline__ uint32_t smem_u32(const void* p) {
    uint32_t a;
    asm("{ .reg .u64 t; cvta.to.shared.u64 t, %1; cvt.u32.u64 %0, t; }"
        : "=r"(a) : "l"(p));
    return a;
}
__device__ __forceinline__ uint32_t mapa32(uint32_t laddr, uint32_t rank) {
    uint32_t ra;
    asm("mapa.shared::cluster.u32 %0, %1, %2;" : "=r"(ra) : "r"(laddr), "r"(rank));
    return ra;
}
__device__ __forceinline__ void mbar_init(uint32_t mbar, uint32_t cnt) {
    asm volatile("mbarrier.init.shared::cta.b64 [%0], %1;" :: "r"(mbar), "r"(cnt) : "memory");
}
__device__ __forceinline__ void mbar_expect(uint32_t mbar, uint32_t tx) {
    asm volatile("mbarrier.arrive.expect_tx.shared::cta.b64 _, [%0], %1;"
                 :: "r"(mbar), "r"(tx) : "memory");
}
__device__ __forceinline__ void mbar_wait(uint32_t mbar, uint32_t parity) {
    asm volatile(
        "{\n\t"
        ".reg .pred P;\n\t"
        "LW%=:\n\t"
        "mbarrier.try_wait.parity.acquire.cluster.shared::cta.b64 P, [%0], %1;\n\t"
        "@P bra LD%=;\n\t"
        "bra LW%=;\n\t"
        "LD%=:\n\t"
        "}"
        :: "r"(mbar), "r"(parity) : "memory");
}
__device__ __forceinline__ void st_async_f32(uint32_t rslot, uint32_t rmbar, float v) {
    asm volatile("st.async.shared::cluster.mbarrier::complete_tx::bytes.b32 [%0], %1, [%2];"
                 :: "r"(rslot), "r"(__float_as_uint(v)), "r"(rmbar) : "memory");
}
__device__ __forceinline__ void cluster_sync_() {
    asm volatile("barrier.cluster.arrive.aligned;" ::: "memory");
    asm volatile("barrier.cluster.wait.aligned;" ::: "memory");
}

template<int CSZ>
__global__ void __launch_bounds__(1024, 1) __cluster_dims__(CSZ, 1, 1)
wave_kernel(const float* __restrict__ xin,   // (NS, NT)
            const float* __restrict__ vp,    // (NZ, NX)
            const int*   __restrict__ src_z, // (NS,)
            const int*   __restrict__ src_x, // (NS,)
            const int*   __restrict__ rec_z, // (NS, NR)
            const int*   __restrict__ rec_x, // (NS, NR)
            float*       __restrict__ out)   // (NS, NT, NR, 1)
{
    constexpr int RPC  = NZ / CSZ;      // rows per CTA
    constexpr int RPT  = RPC / NG;      // rows per thread
    constexpr int ROWS = RPC + 2;       // + halo rows 0 and ROWS-1
    extern __shared__ float smem[];     // [2][ROWS][S]
    __shared__ __align__(8) uint64_t mbars[4];  // [0/1]=top par, [2/3]=bot par
    __shared__ int   rcnt;
    __shared__ int   rpos[NR];
    __shared__ short rid[NR];

    const int tid = threadIdx.x;
    const int g   = tid >> 8;           // row group 0..3 (top..bottom)
    const int x   = tid & 255;
    const int xi  = x + 1;
    const int s   = blockIdx.x / CSZ;   // shot
    uint32_t rank;
    asm("mov.u32 %0, %%cluster_ctarank;" : "=r"(rank));
    const int r0  = (int)rank * RPC;    // first owned global row of CTA
    const int gz0 = g * RPT;            // first CTA-local row of this group

    for (int i = tid; i < 2 * ROWS * S; i += 1024) smem[i] = 0.0f;
    if (tid == 0) {
        rcnt = 0;
        for (int i = 0; i < 4; i++) mbar_init(smem_u32(&mbars[i]), 1);
    }
    __syncthreads();
    cluster_sync_();                    // mbars initialized cluster-wide

    if (tid < NR) {
        int rz = rec_z[s * NR + tid];
        if (rz >= r0 && rz < r0 + RPC) {
            int i = atomicAdd(&rcnt, 1);
            rpos[i] = (rz - r0 + 1) * S + rec_x[s * NR + tid] + 1;
            rid[i]  = (short)tid;
        }
    }

    const int  srcz   = src_z[s];
    const int  srcx   = src_x[s];
    const int  szc    = srcz - r0;                 // CTA-local source row
    const bool my_src = (szc >= gz0 && szc < gz0 + RPT) && (x == srcx);
    const int  szl    = szc - gz0;                 // group-local source row

    float c2h[RPT], ccur[RPT], cold[RPT];
#pragma unroll
    for (int z = 0; z < RPT; z++) {
        float a = vp[(r0 + gz0 + z) * NX + x] * 0.001f;
        c2h[z] = (a * a) * 0.01f;
        ccur[z] = 0.0f;
        cold[z] = 0.0f;
    }
    __syncthreads();

    float* b0 = smem;
    float* b1 = smem + ROWS * S;
    const uint32_t base[2]   = { smem_u32(b0), smem_u32(b1) };
    const uint32_t mb_top[2] = { smem_u32(&mbars[0]), smem_u32(&mbars[1]) };
    const uint32_t mb_bot[2] = { smem_u32(&mbars[2]), smem_u32(&mbars[3]) };
    const bool has_up = (rank > 0);
    const bool has_dn = (rank < CSZ - 1);
    const bool gtop   = (g == 0);
    const bool gbot   = (g == NG - 1);

    for (int t = 0; t < NT; t++) {
        const int par = t & 1;
        float* pcur = par ? b1 : b0;                // p_t mirror
        float* pnxt = par ? b0 : b1;                // receives p_{t+1}
        const uint32_t rbase = base[par ^ 1];       // remote buffer written now

        if (tid == 0) {                             // expect_tx for phase t
            if (has_up) mbar_expect(mb_top[par], NX * 4);
            if (has_dn) mbar_expect(mb_bot[par], NX * 4);
        }

        float srcval = 0.0f;
        if (my_src) srcval = (__ldg(&xin[s * NT + t]) * 0.001f) * 0.001f;

        // ---- batched l/r preload (independent LDS, full MLP) ----
        float lv[RPT], rv[RPT];
#pragma unroll
        for (int z = 0; z < RPT; z++) {
            const int row = gz0 + z + 1;
            lv[z] = pcur[row * S + xi - 1];
            rv[z] = pcur[row * S + xi + 1];
        }

        if (gtop) {
            const float aboveSeam = pcur[(RPT + 1) * S + xi];   // group 1 seam (p_t)
            const float save1 = ccur[1];
            float below = ccur[0];
#pragma unroll
            for (int z = 1; z < RPT; z++) {
                float cz = ccur[z];
                float above = (z == RPT - 1) ? aboveSeam : ccur[z + 1];
                float val = 2.0f * cz - cold[z]
                          + c2h[z] * ((below + above) + (lv[z] + rv[z]) - 4.0f * cz);
                if (my_src && z == szl) val += srcval;
                cold[z] = cz; ccur[z] = val;
                pnxt[(z + 1) * S + xi] = val;
                below = cz;
            }
            if (has_up && t > 0) mbar_wait(mb_top[(t - 1) & 1], ((t - 1) >> 1) & 1);
            {   // row 0
                float cz = ccur[0];
                float haloT = pcur[0 * S + xi];
                float val = 2.0f * cz - cold[0]
                          + c2h[0] * ((haloT + save1) + (lv[0] + rv[0]) - 4.0f * cz);
                if (my_src && szl == 0) val += srcval;
                cold[0] = cz; ccur[0] = val;
                pnxt[1 * S + xi] = val;
                if (has_up) {
                    uint32_t rs = mapa32(rbase + (uint32_t)((ROWS - 1) * S + xi) * 4u, rank - 1);
                    uint32_t rm = mapa32(mb_bot[par], rank - 1);
                    st_async_f32(rs, rm, val);
                }
            }
        } else if (gbot) {
            const float belowSeam = pcur[gz0 * S + xi];         // group NG-2 seam
            float below = belowSeam;
            float saveB = ccur[RPT - 2];
#pragma unroll
            for (int z = 0; z < RPT - 1; z++) {
                float cz = ccur[z];
                float above = ccur[z + 1];
                const int row = gz0 + z + 1;
                float val = 2.0f * cz - cold[z]
                          + c2h[z] * ((below + above) + (lv[z] + rv[z]) - 4.0f * cz);
                if (my_src && z == szl) val += srcval;
                cold[z] = cz; ccur[z] = val;
                pnxt[row * S + xi] = val;
                below = cz;
            }
            if (has_dn && t > 0) mbar_wait(mb_bot[(t - 1) & 1], ((t - 1) >> 1) & 1);
            {   // last row
                constexpr int z = RPT - 1;
                float cz = ccur[z];
                float haloB = pcur[(ROWS - 1) * S + xi];
                float val = 2.0f * cz - cold[z]
                          + c2h[z] * ((saveB + haloB) + (lv[z] + rv[z]) - 4.0f * cz);
                if (my_src && z == szl) val += srcval;
                cold[z] = cz; ccur[z] = val;
                pnxt[RPC * S + xi] = val;
                if (has_dn) {
                    uint32_t rs = mapa32(rbase + (uint32_t)(0 * S + xi) * 4u, rank + 1);
                    uint32_t rm = mapa32(mb_top[par], rank + 1);
                    st_async_f32(rs, rm, val);
                }
            }
        } else {
            const float belowSeam = pcur[gz0 * S + xi];
            const float aboveSeam = pcur[(gz0 + RPT + 1) * S + xi];
            float below = belowSeam;
#pragma unroll
            for (int z = 0; z < RPT; z++) {
                float cz = ccur[z];
                float above = (z == RPT - 1) ? aboveSeam : ccur[z + 1];
                const int row = gz0 + z + 1;
                float val = 2.0f * cz - cold[z]
                          + c2h[z] * ((below + above) + (lv[z] + rv[z]) - 4.0f * cz);
                if (my_src && z == szl) val += srcval;
                cold[z] = cz; ccur[z] = val;
                pnxt[row * S + xi] = val;
                below = cz;
            }
        }

        __syncthreads();                            // pnxt complete locally

        for (int i = tid; i < rcnt; i += 1024)
            out[(s * NT + t) * NR + rid[i]] = pnxt[rpos[i]];
    }

    // drain final phase so no st.async targets our smem after exit
    if (tid == 0) {
        const uint32_t fp = (NT - 1) & 1, fpar = ((NT - 1) >> 1) & 1;
        if (has_up) mbar_wait(mb_top[fp], fpar);
        if (has_dn) mbar_wait(mb_bot[fp], fpar);
    }
    __syncthreads();
    cluster_sync_();
}

template<int CSZ>
static void launch_variant(const float* x, const float* vp, const int* sz,
                           const int* sx, const int* rz, const int* rx, float* out)
{
    const int smemb = 2 * (NZ / CSZ + 2) * S * (int)sizeof(float);
    cudaFuncSetAttribute(wave_kernel<CSZ>,
                         cudaFuncAttributeMaxDynamicSharedMemorySize, smemb);
    wave_kernel<CSZ><<<NS * CSZ, 1024, smemb>>>(x, vp, sz, sx, rz, rx, out);
}

extern "C" void kernel_launch(void* const* d_in, const int* in_sizes, int n_in,
                              void* d_out, int out_size)
{
    const float* x     = (const float*)d_in[0];
    const float* vp    = (const float*)d_in[1];
    const int*   src_z = (const int*)d_in[2];
    const int*   src_x = (const int*)d_in[3];
    const int*   rec_z = (const int*)d_in[4];
    const int*   rec_x = (const int*)d_in[5];
    float*       out   = (float*)d_out;

    const int smem16 = 2 * (NZ / 16 + 2) * S * (int)sizeof(float);
    bool use16 = false;
    if (cudaFuncSetAttribute(wave_kernel<16>,
            cudaFuncAttributeNonPortableClusterSizeAllowed, 1) == cudaSuccess &&
        cudaFuncSetAttribute(wave_kernel<16>,
            cudaFuncAttributeMaxDynamicSharedMemorySize, smem16) == cudaSuccess) {
        cudaLaunchConfig_t cfg = {};
        cfg.gridDim  = dim3(NS * 16, 1, 1);
        cfg.blockDim = dim3(1024, 1, 1);
        cfg.dynamicSmemBytes = (size_t)smem16;
        cudaLaunchAttribute attr[1];
        attr[0].id = cudaLaunchAttributeClusterDimension;
        attr[0].val.clusterDim = {16, 1, 1};
        cfg.attrs = attr;
        cfg.numAttrs = 1;
        int ncl = 0;
        if (cudaOccupancyMaxActiveClusters(&ncl, wave_kernel<16>, &cfg) == cudaSuccess
            && ncl >= NS) use16 = true;
        else cudaGetLastError();
    } else {
        cudaGetLastError();
    }

    if (use16) launch_variant<16>(x, vp, src_z, src_x, rec_z, rec_x, out);
    else       launch_variant<8>(x, vp, src_z, src_x, rec_z, rec_x, out);
}

// round 6
// speedup vs baseline: 10.7389x; 1.1251x over previous
#include <cuda_runtime.h>
#include <cstdint>

// 2D acoustic FDTD, 4 shots x 512 steps, 256x256 grid.
// One cluster per shot, CSZ CTAs x 1024 threads. 128 column-PAIR threads x
// NG=8 row groups; each thread updates RPT rows x 2 cols with packed f32x2
// math (FFMA2). p_t / -p_{t-1} column pairs in registers; smem mirror gives
// left/right + seams + halos (all 64-bit, aligned, conflict-free).
// Halo rows pushed to neighbor CTAs with st.async.b64 + parity mbarriers.

#define NS    4
#define NT    512
#define NZ    256
#define NX    256
#define NR    128
#define S     260          // padded row stride: cols [2..257] live, pads 0
#define NG    8            // row groups (1024 threads / 128 col-pairs)

typedef unsigned long long u64;

__device__ __forceinline__ uint32_t smem_u32(const void* p) {
    uint32_t a;
    asm("{ .reg .u64 t; cvta.to.shared.u64 t, %1; cvt.u32.u64 %0, t; }"
        : "=r"(a) : "l"(p));
    return a;
}
__device__ __forceinline__ uint32_t mapa32(uint32_t laddr, uint32_t rank) {
    uint32_t ra;
    asm("mapa.shared::cluster.u32 %0, %1, %2;" : "=r"(ra) : "r"(laddr), "r"(rank));
    return ra;
}
__device__ __forceinline__ void mbar_init(uint32_t mbar, uint32_t cnt) {
    asm volatile("mbarrier.init.shared::cta.b64 [%0], %1;" :: "r"(mbar), "r"(cnt) : "memory");
}
__device__ __forceinline__ void mbar_expect(uint32_t mbar, uint32_t tx) {
    asm volatile("mbarrier.arrive.expect_tx.shared::cta.b64 _, [%0], %1;"
                 :: "r"(mbar), "r"(tx) : "memory");
}
__device__ __forceinline__ void mbar_wait(uint32_t mbar, uint32_t parity) {
    asm volatile(
        "{\n\t"
        ".reg .pred P;\n\t"
        "LW%=:\n\t"
        "mbarrier.try_wait.parity.acquire.cluster.shared::cta.b64 P, [%0], %1;\n\t"
        "@P bra LD%=;\n\t"
        "bra LW%=;\n\t"
        "LD%=:\n\t"
        "}"
        :: "r"(mbar), "r"(parity) : "memory");
}
__device__ __forceinline__ void st_async_f2(uint32_t rslot, uint32_t rmbar, u64 v) {
    asm volatile("st.async.shared::cluster.mbarrier::complete_tx::bytes.b64 [%0], %1, [%2];"
                 :: "r"(rslot), "l"(v), "r"(rmbar) : "memory");
}
__device__ __forceinline__ void cluster_sync_() {
    asm volatile("barrier.cluster.arrive.aligned;" ::: "memory");
    asm volatile("barrier.cluster.wait.aligned;" ::: "memory");
}

// ---- packed f32x2 helpers ----
__device__ __forceinline__ u64 f2pack(float lo, float hi) {
    u64 r; asm("mov.b64 %0, {%1, %2};" : "=l"(r) : "f"(lo), "f"(hi)); return r;
}
__device__ __forceinline__ void f2unpack(u64 v, float& lo, float& hi) {
    asm("mov.b64 {%0, %1}, %2;" : "=f"(lo), "=f"(hi) : "l"(v));
}
__device__ __forceinline__ u64 f2add(u64 a, u64 b) {
    u64 r; asm("add.rn.f32x2 %0, %1, %2;" : "=l"(r) : "l"(a), "l"(b)); return r;
}
__device__ __forceinline__ u64 f2mul(u64 a, u64 b) {
    u64 r; asm("mul.rn.f32x2 %0, %1, %2;" : "=l"(r) : "l"(a), "l"(b)); return r;
}
__device__ __forceinline__ u64 f2fma(u64 a, u64 b, u64 c) {
    u64 r; asm("fma.rn.f32x2 %0, %1, %2, %3;" : "=l"(r) : "l"(a), "l"(b), "l"(c)); return r;
}
__device__ __forceinline__ u64 f2ld(const float* p) {        // aligned LDS.64
    float2 v = *(const float2*)p; return f2pack(v.x, v.y);
}
__device__ __forceinline__ void f2st(float* p, u64 v) {      // aligned STS.64
    float lo, hi; f2unpack(v, lo, hi);
    *(float2*)p = make_float2(lo, hi);
}

template<int CSZ>
__global__ void __launch_bounds__(1024, 1) __cluster_dims__(CSZ, 1, 1)
wave_kernel(const float* __restrict__ xin,   // (NS, NT)
            const float* __restrict__ vp,    // (NZ, NX)
            const int*   __restrict__ src_z, // (NS,)
            const int*   __restrict__ src_x, // (NS,)
            const int*   __restrict__ rec_z, // (NS, NR)
            const int*   __restrict__ rec_x, // (NS, NR)
            float*       __restrict__ out)   // (NS, NT, NR, 1)
{
    constexpr int RPC  = NZ / CSZ;      // rows per CTA
    constexpr int RPT  = RPC / NG;      // rows per thread
    constexpr int ROWS = RPC + 2;       // + halo rows 0 and ROWS-1
    extern __shared__ float smem[];     // [2][ROWS][S]
    __shared__ __align__(8) uint64_t mbars[4];  // [0/1]=top par, [2/3]=bot par
    __shared__ int   rcnt;
    __shared__ int   rpos[NR];
    __shared__ short rid[NR];

    const int tid = threadIdx.x;
    const int g   = tid >> 7;           // row group 0..7
    const int tx  = tid & 127;          // column-pair index
    const int xi  = 2 + 2 * tx;         // first element col of pair
    const int s   = blockIdx.x / CSZ;   // shot
    uint32_t rank;
    asm("mov.u32 %0, %%cluster_ctarank;" : "=r"(rank));
    const int r0  = (int)rank * RPC;    // first owned global row of CTA
    const int gz0 = g * RPT;            // first CTA-local row of this group

    for (int i = tid; i < 2 * ROWS * S; i += 1024) smem[i] = 0.0f;
    if (tid == 0) {
        rcnt = 0;
        for (int i = 0; i < 4; i++) mbar_init(smem_u32(&mbars[i]), 1);
    }
    __syncthreads();
    cluster_sync_();                    // mbars initialized cluster-wide

    if (tid < NR) {
        int rz = rec_z[s * NR + tid];
        if (rz >= r0 && rz < r0 + RPC) {
            int i = atomicAdd(&rcnt, 1);
            rpos[i] = (rz - r0 + 1) * S + rec_x[s * NR + tid] + 2;
            rid[i]  = (short)tid;
        }
    }

    const int  srcz    = src_z[s];
    const int  srcx    = src_x[s];
    const int  szc     = srcz - r0;                 // CTA-local source row
    const bool my_src  = (szc >= gz0 && szc < gz0 + RPT) && (tx == (srcx >> 1));
    const int  szl     = szc - gz0;                 // group-local source row
    const int  srclane = srcx & 1;

    u64 c2p[RPT], ccp[RPT], nco[RPT];               // packed pairs per row
#pragma unroll
    for (int z = 0; z < RPT; z++) {
        float a0 = vp[(r0 + gz0 + z) * NX + 2 * tx]     * 0.001f;
        float a1 = vp[(r0 + gz0 + z) * NX + 2 * tx + 1] * 0.001f;
        c2p[z] = f2pack((a0 * a0) * 0.01f, (a1 * a1) * 0.01f);
        ccp[z] = 0ull;
        nco[z] = 0ull;                              // -p_{t-1} = -0
    }
    __syncthreads();

    float* b0 = smem;
    float* b1 = smem + ROWS * S;
    const uint32_t base[2]   = { smem_u32(b0), smem_u32(b1) };
    const uint32_t mb_top[2] = { smem_u32(&mbars[0]), smem_u32(&mbars[1]) };
    const uint32_t mb_bot[2] = { smem_u32(&mbars[2]), smem_u32(&mbars[3]) };
    const bool has_up = (rank > 0);
    const bool has_dn = (rank < CSZ - 1);
    const bool gtop   = (g == 0);
    const bool gbot   = (g == NG - 1);

    const u64 NEG4 = f2pack(-4.0f, -4.0f);
    const u64 TWO  = f2pack( 2.0f,  2.0f);
    const u64 NEG1 = f2pack(-1.0f, -1.0f);

    const int off0   = (gz0 + 1) * S + xi;          // smem offset of first owned row
    const int offSB  = gz0 * S + xi;                // seam/halo below
    const int offSA  = (gz0 + RPT + 1) * S + xi;    // seam/halo above

// one row update; 'below'/'above' are packed pairs of p_t; returns new val,
// leaves old cc in 'oldcc' for the vertical carry.
#define STEP_ROW(z, below, above, oldcc, val)                                  \
    {                                                                          \
        u64 cc = ccp[z];                                                       \
        float clo, chi; f2unpack(cc, clo, chi);                                \
        u64 vert = f2add(below, above);                                        \
        u64 horz = f2add(f2pack(lv[z], clo), f2pack(chi, rv[z]));              \
        u64 sum  = f2add(vert, horz);                                          \
        u64 lap  = f2fma(cc, NEG4, sum);                                       \
        u64 tmp  = f2fma(cc, TWO, nco[z]);                                     \
        val = f2fma(c2p[z], lap, tmp);                                         \
        nco[z] = f2mul(cc, NEG1);                                              \
        if (my_src && (z) == szl) {                                            \
            float a, b; f2unpack(val, a, b);                                   \
            if (srclane) b += srcval; else a += srcval;                        \
            val = f2pack(a, b);                                                \
        }                                                                      \
        ccp[z] = val;                                                          \
        f2st(pnxt + off0 + (z) * S, val);                                      \
        oldcc = cc;                                                            \
    }

    for (int t = 0; t < NT; t++) {
        const int par = t & 1;
        float* pcur = par ? b1 : b0;                // p_t mirror
        float* pnxt = par ? b0 : b1;                // receives p_{t+1}
        const uint32_t rbase = base[par ^ 1];       // remote buffer written now

        if (tid == 0) {                             // expect_tx for phase t
            if (has_up) mbar_expect(mb_top[par], NX * 4);
            if (has_dn) mbar_expect(mb_bot[par], NX * 4);
        }

        float srcval = 0.0f;
        if (my_src) srcval = (__ldg(&xin[s * NT + t]) * 0.001f) * 0.001f;

        // batched left/right preload: aligned pair loads, keep one lane each
        float lv[RPT], rv[RPT];
#pragma unroll
        for (int z = 0; z < RPT; z++) {
            float2 a = *(const float2*)(pcur + off0 + z * S - 2);
            float2 b = *(const float2*)(pcur + off0 + z * S + 2);
            lv[z] = a.y; rv[z] = b.x;
        }

        u64 oldcc, val;
        if (gtop) {
            const u64 seamA = f2ld(pcur + offSA);
            const u64 save1 = ccp[1];               // old row-1 pair for row 0
            u64 below = ccp[0];
#pragma unroll
            for (int z = 1; z < RPT; z++) {
                u64 above = (z == RPT - 1) ? seamA : ccp[z + 1];
                STEP_ROW(z, below, above, oldcc, val);
                below = oldcc;
            }
            if (has_up && t > 0) mbar_wait(mb_top[(t - 1) & 1], ((t - 1) >> 1) & 1);
            {
                const u64 haloB = f2ld(pcur + offSB);   // halo row 0
                STEP_ROW(0, haloB, save1, oldcc, val);
                if (has_up) {
                    uint32_t rs = mapa32(rbase + (uint32_t)((ROWS - 1) * S + xi) * 4u, rank - 1);
                    uint32_t rm = mapa32(mb_bot[par], rank - 1);
                    st_async_f2(rs, rm, val);
                }
            }
        } else if (gbot) {
            const u64 seamB = f2ld(pcur + offSB);
            u64 below = seamB;
#pragma unroll
            for (int z = 0; z < RPT - 1; z++) {
                u64 above = ccp[z + 1];
                STEP_ROW(z, below, above, oldcc, val);
                below = oldcc;
            }
            if (has_dn && t > 0) mbar_wait(mb_bot[(t - 1) & 1], ((t - 1) >> 1) & 1);
            {
                const u64 haloA = f2ld(pcur + offSA);   // halo row ROWS-1
                STEP_ROW(RPT - 1, below, haloA, oldcc, val);
                if (has_dn) {
                    uint32_t rs = mapa32(rbase + (uint32_t)(S + xi) * 4u, rank + 1); // row 1... 
                    // NOTE: down neighbor's TOP HALO is its smem row 0:
                    rs = mapa32(rbase + (uint32_t)(0 * S + xi) * 4u, rank + 1);
                    uint32_t rm = mapa32(mb_top[par], rank + 1);
                    st_async_f2(rs, rm, val);
                }
            }
        } else {
            const u64 seamB = f2ld(pcur + offSB);
            const u64 seamA = f2ld(pcur + offSA);
            u64 below = seamB;
#pragma unroll
            for (int z = 0; z < RPT; z++) {
                u64 above = (z == RPT - 1) ? seamA : ccp[z + 1];
                STEP_ROW(z, below, above, oldcc, val);
                below = oldcc;
            }
        }

        __syncthreads();                            // pnxt complete locally

        for (int i = tid; i < rcnt; i += 1024)
            out[(s * NT + t) * NR + rid[i]] = pnxt[rpos[i]];
    }

    // drain final phase so no st.async targets our smem after exit
    if (tid == 0) {
        const uint32_t fp = (NT - 1) & 1, fpar = ((NT - 1) >> 1) & 1;
        if (has_up) mbar_wait(mb_top[fp], fpar);
        if (has_dn) mbar_wait(mb_bot[fp], fpar);
    }
    __syncthreads();
    cluster_sync_();
#undef STEP_ROW
}

template<int CSZ>
static void launch_variant(const float* x, const float* vp, const int* sz,
                           const int* sx, const int* rz, const int* rx, float* out)
{
    const int smemb = 2 * (NZ / CSZ + 2) * S * (int)sizeof(float);
    cudaFuncSetAttribute(wave_kernel<CSZ>,
                         cudaFuncAttributeMaxDynamicSharedMemorySize, smemb);
    wave_kernel<CSZ><<<NS * CSZ, 1024, smemb>>>(x, vp, sz, sx, rz, rx, out);
}

extern "C" void kernel_launch(void* const* d_in, const int* in_sizes, int n_in,
                              void* d_out, int out_size)
{
    const float* x     = (const float*)d_in[0];
    const float* vp    = (const float*)d_in[1];
    const int*   src_z = (const int*)d_in[2];
    const int*   src_x = (const int*)d_in[3];
    const int*   rec_z = (const int*)d_in[4];
    const int*   rec_x = (const int*)d_in[5];
    float*       out   = (float*)d_out;

    const int smem16 = 2 * (NZ / 16 + 2) * S * (int)sizeof(float);
    bool use16 = false;
    if (cudaFuncSetAttribute(wave_kernel<16>,
            cudaFuncAttributeNonPortableClusterSizeAllowed, 1) == cudaSuccess &&
        cudaFuncSetAttribute(wave_kernel<16>,
            cudaFuncAttributeMaxDynamicSharedMemorySize, smem16) == cudaSuccess) {
        cudaLaunchConfig_t cfg = {};
        cfg.gridDim  = dim3(NS * 16, 1, 1);
        cfg.blockDim = dim3(1024, 1, 1);
        cfg.dynamicSmemBytes = (size_t)smem16;
        cudaLaunchAttribute attr[1];
        attr[0].id = cudaLaunchAttributeClusterDimension;
        attr[0].val.clusterDim = {16, 1, 1};
        cfg.attrs = attr;
        cfg.numAttrs = 1;
        int ncl = 0;
        if (cudaOccupancyMaxActiveClusters(&ncl, wave_kernel<16>, &cfg) == cudaSuccess
            && ncl >= NS) use16 = true;
        else cudaGetLastError();
    } else {
        cudaGetLastError();
    }

    if (use16) launch_variant<16>(x, vp, src_z, src_x, rec_z, rec_x, out);
    else       launch_variant<8>(x, vp, src_z, src_x, rec_z, rec_x, out);
}

// round 7
// speedup vs baseline: 12.6952x; 1.1822x over previous
#include <cuda_runtime.h>
#include <cstdint>

// 2D acoustic FDTD, 4 shots x 512 steps, 256x256 grid.
// One cluster per shot, CSZ CTAs x 1024 threads. 128 column-PAIR threads x
// NG row groups; packed f32x2 math (FFMA2). p_t / -p_{t-1} pairs in
// registers; smem mirror gives left/right + seams + halos. Halo rows pushed
// with st.async.b64 + parity mbarriers. Time loop unrolled x2 with fixed
// buffer roles; single predicated receiver store.

#define NS    4
#define NT    512
#define NZ    256
#define NX    256
#define NR    128
#define S     260          // padded row stride: cols [2..257] live, pads 0
#define NG    8            // row groups (1024 threads / 128 col-pairs)

typedef unsigned long long u64;

__device__ __forceinline__ uint32_t smem_u32(const void* p) {
    uint32_t a;
    asm("{ .reg .u64 t; cvta.to.shared.u64 t, %1; cvt.u32.u64 %0, t; }"
        : "=r"(a) : "l"(p));
    return a;
}
__device__ __forceinline__ uint32_t mapa32(uint32_t laddr, uint32_t rank) {
    uint32_t ra;
    asm("mapa.shared::cluster.u32 %0, %1, %2;" : "=r"(ra) : "r"(laddr), "r"(rank));
    return ra;
}
__device__ __forceinline__ void mbar_init(uint32_t mbar, uint32_t cnt) {
    asm volatile("mbarrier.init.shared::cta.b64 [%0], %1;" :: "r"(mbar), "r"(cnt) : "memory");
}
__device__ __forceinline__ void mbar_expect(uint32_t mbar, uint32_t tx) {
    asm volatile("mbarrier.arrive.expect_tx.shared::cta.b64 _, [%0], %1;"
                 :: "r"(mbar), "r"(tx) : "memory");
}
__device__ __forceinline__ void mbar_wait(uint32_t mbar, uint32_t parity) {
    asm volatile(
        "{\n\t"
        ".reg .pred P;\n\t"
        "LW%=:\n\t"
        "mbarrier.try_wait.parity.acquire.cluster.shared::cta.b64 P, [%0], %1;\n\t"
        "@P bra LD%=;\n\t"
        "bra LW%=;\n\t"
        "LD%=:\n\t"
        "}"
        :: "r"(mbar), "r"(parity) : "memory");
}
__device__ __forceinline__ void st_async_f2(uint32_t rslot, uint32_t rmbar, u64 v) {
    asm volatile("st.async.shared::cluster.mbarrier::complete_tx::bytes.b64 [%0], %1, [%2];"
                 :: "r"(rslot), "l"(v), "r"(rmbar) : "memory");
}
__device__ __forceinline__ void cluster_sync_() {
    asm volatile("barrier.cluster.arrive.aligned;" ::: "memory");
    asm volatile("barrier.cluster.wait.aligned;" ::: "memory");
}

// ---- packed f32x2 helpers ----
__device__ __forceinline__ u64 f2pack(float lo, float hi) {
    u64 r; asm("mov.b64 %0, {%1, %2};" : "=l"(r) : "f"(lo), "f"(hi)); return r;
}
__device__ __forceinline__ void f2unpack(u64 v, float& lo, float& hi) {
    asm("mov.b64 {%0, %1}, %2;" : "=f"(lo), "=f"(hi) : "l"(v));
}
__device__ __forceinline__ u64 f2add(u64 a, u64 b) {
    u64 r; asm("add.rn.f32x2 %0, %1, %2;" : "=l"(r) : "l"(a), "l"(b)); return r;
}
__device__ __forceinline__ u64 f2mul(u64 a, u64 b) {
    u64 r; asm("mul.rn.f32x2 %0, %1, %2;" : "=l"(r) : "l"(a), "l"(b)); return r;
}
__device__ __forceinline__ u64 f2fma(u64 a, u64 b, u64 c) {
    u64 r; asm("fma.rn.f32x2 %0, %1, %2, %3;" : "=l"(r) : "l"(a), "l"(b), "l"(c)); return r;
}
__device__ __forceinline__ u64 f2ld(const float* p) {        // aligned LDS.64
    float2 v = *(const float2*)p; return f2pack(v.x, v.y);
}
__device__ __forceinline__ void f2st(float* p, u64 v) {      // aligned STS.64
    float lo, hi; f2unpack(v, lo, hi);
    *(float2*)p = make_float2(lo, hi);
}

template<int CSZ>
__global__ void __launch_bounds__(1024, 1) __cluster_dims__(CSZ, 1, 1)
wave_kernel(const float* __restrict__ xin,   // (NS, NT)
            const float* __restrict__ vp,    // (NZ, NX)
            const int*   __restrict__ src_z, // (NS,)
            const int*   __restrict__ src_x, // (NS,)
            const int*   __restrict__ rec_z, // (NS, NR)
            const int*   __restrict__ rec_x, // (NS, NR)
            float*       __restrict__ out)   // (NS, NT, NR, 1)
{
    constexpr int RPC  = NZ / CSZ;      // rows per CTA
    constexpr int RPT  = RPC / NG;      // rows per thread
    constexpr int ROWS = RPC + 2;       // + halo rows 0 and ROWS-1
    extern __shared__ float smem[];     // [2][ROWS][S]
    __shared__ __align__(8) uint64_t mbars[4];  // [0/1]=top par, [2/3]=bot par
    __shared__ int   rcnt;
    __shared__ int   rpos[NR];
    __shared__ short rid[NR];

    const int tid = threadIdx.x;
    const int g   = tid >> 7;           // row group
    const int tx  = tid & 127;          // column-pair index
    const int xi  = 2 + 2 * tx;         // first element col of pair
    const int s   = blockIdx.x / CSZ;   // shot
    uint32_t rank;
    asm("mov.u32 %0, %%cluster_ctarank;" : "=r"(rank));
    const int r0  = (int)rank * RPC;
    const int gz0 = g * RPT;

    for (int i = tid; i < 2 * ROWS * S; i += 1024) smem[i] = 0.0f;
    if (tid == 0) {
        rcnt = 0;
        for (int i = 0; i < 4; i++) mbar_init(smem_u32(&mbars[i]), 1);
    }
    __syncthreads();
    cluster_sync_();                    // mbars initialized cluster-wide

    if (tid < NR) {
        int rz = rec_z[s * NR + tid];
        if (rz >= r0 && rz < r0 + RPC) {
            int i = atomicAdd(&rcnt, 1);
            rpos[i] = (rz - r0 + 1) * S + rec_x[s * NR + tid] + 2;
            rid[i]  = (short)tid;
        }
    }

    const int  srcz    = src_z[s];
    const int  srcx    = src_x[s];
    const int  szc     = srcz - r0;
    const bool my_src  = (szc >= gz0 && szc < gz0 + RPT) && (tx == (srcx >> 1));
    const int  szl     = szc - gz0;
    const int  srclane = srcx & 1;

    u64 c2p[RPT], ccp[RPT], nco[RPT];
#pragma unroll
    for (int z = 0; z < RPT; z++) {
        float a0 = vp[(r0 + gz0 + z) * NX + 2 * tx]     * 0.001f;
        float a1 = vp[(r0 + gz0 + z) * NX + 2 * tx + 1] * 0.001f;
        c2p[z] = f2pack((a0 * a0) * 0.01f, (a1 * a1) * 0.01f);
        ccp[z] = 0ull;
        nco[z] = 0ull;                  // -p_{t-1}
    }
    __syncthreads();

    float* const b0 = smem;
    float* const b1 = smem + ROWS * S;
    const uint32_t base0 = smem_u32(b0);
    const uint32_t base1 = smem_u32(b1);
    const uint32_t mb_top[2] = { smem_u32(&mbars[0]), smem_u32(&mbars[1]) };
    const uint32_t mb_bot[2] = { smem_u32(&mbars[2]), smem_u32(&mbars[3]) };
    const bool has_up = (rank > 0);
    const bool has_dn = (rank < CSZ - 1);
    const bool gtop   = (g == 0);
    const bool gbot   = (g == NG - 1);

    const u64 NEG4 = f2pack(-4.0f, -4.0f);
    const u64 TWO  = f2pack( 2.0f,  2.0f);
    const u64 NEG1 = f2pack(-1.0f, -1.0f);

    const int off0  = (gz0 + 1) * S + xi;
    const int offSB = gz0 * S + xi;
    const int offSA = (gz0 + RPT + 1) * S + xi;

#define STEP_ROW(PN, z, below, above, oldcc, val)                              \
    {                                                                          \
        u64 cc = ccp[z];                                                       \
        float clo, chi; f2unpack(cc, clo, chi);                                \
        u64 vert = f2add(below, above);                                        \
        u64 horz = f2add(f2pack(lv[z], clo), f2pack(chi, rv[z]));              \
        u64 sum  = f2add(vert, horz);                                          \
        u64 lap  = f2fma(cc, NEG4, sum);                                       \
        u64 tmp  = f2fma(cc, TWO, nco[z]);                                     \
        val = f2fma(c2p[z], lap, tmp);                                         \
        nco[z] = f2mul(cc, NEG1);                                              \
        if (my_src && (z) == szl) {                                            \
            float a, b; f2unpack(val, a, b);                                   \
            if (srclane) b += srcval; else a += srcval;                        \
            val = f2pack(a, b);                                                \
        }                                                                      \
        ccp[z] = val;                                                          \
        f2st((PN) + off0 + (z) * S, val);                                      \
        oldcc = cc;                                                            \
    }

// One full phase. PCUR/PNXT are compile-time-fixed buffer pointers, PAR the
// literal phase parity (PNXT's base index is PAR^1), T the step, WAITOK
// whether a previous phase exists, WPAR the mbar phase parity of step T-1.
#define DO_STEP(PCUR, PNXT, RBASE, PAR, T, WAITOK, WPAR)                       \
    {                                                                          \
        if (tid == 0) {                                                        \
            if (has_up) mbar_expect(mb_top[PAR], NX * 4);                      \
            if (has_dn) mbar_expect(mb_bot[PAR], NX * 4);                      \
        }                                                                      \
        float srcval = 0.0f;                                                   \
        if (my_src) srcval = (__ldg(&xin[s * NT + (T)]) * 0.001f) * 0.001f;    \
        float lv[RPT], rv[RPT];                                                \
        _Pragma("unroll")                                                      \
        for (int z = 0; z < RPT; z++) {                                        \
            float2 a = *(const float2*)((PCUR) + off0 + z * S - 2);            \
            float2 b = *(const float2*)((PCUR) + off0 + z * S + 2);            \
            lv[z] = a.y; rv[z] = b.x;                                          \
        }                                                                      \
        u64 oldcc, val;                                                        \
        if (gtop) {                                                            \
            const u64 seamA = f2ld((PCUR) + offSA);                            \
            const u64 save1 = ccp[1];                                          \
            u64 below = ccp[0];                                                \
            _Pragma("unroll")                                                  \
            for (int z = 1; z < RPT; z++) {                                    \
                u64 above = (z == RPT - 1) ? seamA : ccp[z + 1];               \
                STEP_ROW(PNXT, z, below, above, oldcc, val);                   \
                below = oldcc;                                                 \
            }                                                                  \
            if (has_up && (WAITOK)) mbar_wait(mb_top[(PAR) ^ 1], (WPAR));      \
            {                                                                  \
                const u64 haloB = f2ld((PCUR) + offSB);                        \
                STEP_ROW(PNXT, 0, haloB, save1, oldcc, val);                   \
                if (has_up) {                                                  \
                    uint32_t rs = mapa32((RBASE) +                             \
                        (uint32_t)((ROWS - 1) * S + xi) * 4u, rank - 1);       \
                    uint32_t rm = mapa32(mb_bot[PAR], rank - 1);               \
                    st_async_f2(rs, rm, val);                                  \
                }                                                              \
            }                                                                  \
        } else if (gbot) {                                                     \
            u64 below = f2ld((PCUR) + offSB);                                  \
            _Pragma("unroll")                                                  \
            for (int z = 0; z < RPT - 1; z++) {                                \
                u64 above = ccp[z + 1];                                        \
                STEP_ROW(PNXT, z, below, above, oldcc, val);                   \
                below = oldcc;                                                 \
            }                                                                  \
            if (has_dn && (WAITOK)) mbar_wait(mb_bot[(PAR) ^ 1], (WPAR));      \
            {                                                                  \
                const u64 haloA = f2ld((PCUR) + offSA);                        \
                STEP_ROW(PNXT, RPT - 1, below, haloA, oldcc, val);             \
                if (has_dn) {                                                  \
                    uint32_t rs = mapa32((RBASE) + (uint32_t)(xi) * 4u,        \
                                         rank + 1);                            \
                    uint32_t rm = mapa32(mb_top[PAR], rank + 1);               \
                    st_async_f2(rs, rm, val);                                  \
                }                                                              \
            }                                                                  \
        } else {                                                               \
            const u64 seamA = f2ld((PCUR) + offSA);                            \
            u64 below = f2ld((PCUR) + offSB);                                  \
            _Pragma("unroll")                                                  \
            for (int z = 0; z < RPT; z++) {                                    \
                u64 above = (z == RPT - 1) ? seamA : ccp[z + 1];               \
                STEP_ROW(PNXT, z, below, above, oldcc, val);                   \
                below = oldcc;                                                 \
            }                                                                  \
        }                                                                      \
        __syncthreads();                                                       \
        if (tid < rcnt)                                                        \
            out[(s * NT + (T)) * NR + rid[tid]] = (PNXT)[rpos[tid]];           \
    }

    for (int t = 0; t < NT; t += 2) {
        const uint32_t m = (uint32_t)(t >> 1);
        // step A: t even, par=0, pcur=b0 -> pnxt=b1
        DO_STEP(b0, b1, base1, 0, t, t > 0, (m - 1) & 1);
        // step B: t+1 odd, par=1, pcur=b1 -> pnxt=b0
        DO_STEP(b1, b0, base0, 1, t + 1, true, m & 1);
    }

    // drain final phase so no st.async targets our smem after exit
    if (tid == 0) {
        const uint32_t fp = (NT - 1) & 1, fpar = ((NT - 1) >> 1) & 1;
        if (has_up) mbar_wait(mb_top[fp], fpar);
        if (has_dn) mbar_wait(mb_bot[fp], fpar);
    }
    __syncthreads();
    cluster_sync_();
#undef DO_STEP
#undef STEP_ROW
}

template<int CSZ>
static void launch_variant(const float* x, const float* vp, const int* sz,
                           const int* sx, const int* rz, const int* rx, float* out)
{
    const int smemb = 2 * (NZ / CSZ + 2) * S * (int)sizeof(float);
    cudaFuncSetAttribute(wave_kernel<CSZ>,
                         cudaFuncAttributeMaxDynamicSharedMemorySize, smemb);
    wave_kernel<CSZ><<<NS * CSZ, 1024, smemb>>>(x, vp, sz, sx, rz, rx, out);
}

extern "C" void kernel_launch(void* const* d_in, const int* in_sizes, int n_in,
                              void* d_out, int out_size)
{
    const float* x     = (const float*)d_in[0];
    const float* vp    = (const float*)d_in[1];
    const int*   src_z = (const int*)d_in[2];
    const int*   src_x = (const int*)d_in[3];
    const int*   rec_z = (const int*)d_in[4];
    const int*   rec_x = (const int*)d_in[5];
    float*       out   = (float*)d_out;

    const int smem16 = 2 * (NZ / 16 + 2) * S * (int)sizeof(float);
    bool use16 = false;
    if (cudaFuncSetAttribute(wave_kernel<16>,
            cudaFuncAttributeNonPortableClusterSizeAllowed, 1) == cudaSuccess &&
        cudaFuncSetAttribute(wave_kernel<16>,
            cudaFuncAttributeMaxDynamicSharedMemorySize, smem16) == cudaSuccess) {
        cudaLaunchConfig_t cfg = {};
        cfg.gridDim  = dim3(NS * 16, 1, 1);
        cfg.blockDim = dim3(1024, 1, 1);
        cfg.dynamicSmemBytes = (size_t)smem16;
        cudaLaunchAttribute attr[1];
        attr[0].id = cudaLaunchAttributeClusterDimension;
        attr[0].val.clusterDim = {16, 1, 1};
        cfg.attrs = attr;
        cfg.numAttrs = 1;
        int ncl = 0;
        if (cudaOccupancyMaxActiveClusters(&ncl, wave_kernel<16>, &cfg) == cudaSuccess
            && ncl >= NS) use16 = true;
        else cudaGetLastError();
    } else {
        cudaGetLastError();
    }

    if (use16) launch_variant<16>(x, vp, src_z, src_x, rec_z, rec_x, out);
    else       launch_variant<8>(x, vp, src_z, src_x, rec_z, rec_x, out);
}

// round 8
// speedup vs baseline: 14.5181x; 1.1436x over previous
#include <cuda_runtime.h>
#include <cstdint>

// 2D acoustic FDTD, 4 shots x 512 steps, 256x256 grid.
// One cluster per shot, CSZ CTAs x 1024 threads. 128 column-PAIR threads x
// NG row groups; packed f32x2 math (FFMA2). p_t / -p_{t-1} pairs in
// registers; smem mirror gives left/right + seams + halos. Halo rows pushed
// with st.async.b64 + parity mbarriers, BOUNDARY-FIRST so the push latency
// overlaps interior compute. Time loop unrolled x2, fixed buffer roles,
// register-hoisted receiver stores.

#define NS    4
#define NT    512
#define NZ    256
#define NX    256
#define NR    128
#define S     260          // padded row stride: cols [2..257] live, pads 0
#define NG    8            // row groups (1024 threads / 128 col-pairs)

typedef unsigned long long u64;

__device__ __forceinline__ uint32_t smem_u32(const void* p) {
    uint32_t a;
    asm("{ .reg .u64 t; cvta.to.shared.u64 t, %1; cvt.u32.u64 %0, t; }"
        : "=r"(a) : "l"(p));
    return a;
}
__device__ __forceinline__ uint32_t mapa32(uint32_t laddr, uint32_t rank) {
    uint32_t ra;
    asm("mapa.shared::cluster.u32 %0, %1, %2;" : "=r"(ra) : "r"(laddr), "r"(rank));
    return ra;
}
__device__ __forceinline__ void mbar_init(uint32_t mbar, uint32_t cnt) {
    asm volatile("mbarrier.init.shared::cta.b64 [%0], %1;" :: "r"(mbar), "r"(cnt) : "memory");
}
__device__ __forceinline__ void mbar_expect(uint32_t mbar, uint32_t tx) {
    asm volatile("mbarrier.arrive.expect_tx.shared::cta.b64 _, [%0], %1;"
                 :: "r"(mbar), "r"(tx) : "memory");
}
__device__ __forceinline__ void mbar_wait(uint32_t mbar, uint32_t parity) {
    asm volatile(
        "{\n\t"
        ".reg .pred P;\n\t"
        "LW%=:\n\t"
        "mbarrier.try_wait.parity.acquire.cluster.shared::cta.b64 P, [%0], %1;\n\t"
        "@P bra LD%=;\n\t"
        "bra LW%=;\n\t"
        "LD%=:\n\t"
        "}"
        :: "r"(mbar), "r"(parity) : "memory");
}
__device__ __forceinline__ void st_async_f2(uint32_t rslot, uint32_t rmbar, u64 v) {
    asm volatile("st.async.shared::cluster.mbarrier::complete_tx::bytes.b64 [%0], %1, [%2];"
                 :: "r"(rslot), "l"(v), "r"(rmbar) : "memory");
}
__device__ __forceinline__ void cluster_sync_() {
    asm volatile("barrier.cluster.arrive.aligned;" ::: "memory");
    asm volatile("barrier.cluster.wait.aligned;" ::: "memory");
}

// ---- packed f32x2 helpers ----
__device__ __forceinline__ u64 f2pack(float lo, float hi) {
    u64 r; asm("mov.b64 %0, {%1, %2};" : "=l"(r) : "f"(lo), "f"(hi)); return r;
}
__device__ __forceinline__ void f2unpack(u64 v, float& lo, float& hi) {
    asm("mov.b64 {%0, %1}, %2;" : "=f"(lo), "=f"(hi) : "l"(v));
}
__device__ __forceinline__ u64 f2add(u64 a, u64 b) {
    u64 r; asm("add.rn.f32x2 %0, %1, %2;" : "=l"(r) : "l"(a), "l"(b)); return r;
}
__device__ __forceinline__ u64 f2mul(u64 a, u64 b) {
    u64 r; asm("mul.rn.f32x2 %0, %1, %2;" : "=l"(r) : "l"(a), "l"(b)); return r;
}
__device__ __forceinline__ u64 f2fma(u64 a, u64 b, u64 c) {
    u64 r; asm("fma.rn.f32x2 %0, %1, %2, %3;" : "=l"(r) : "l"(a), "l"(b), "l"(c)); return r;
}
__device__ __forceinline__ u64 f2ld(const float* p) {        // aligned LDS.64
    float2 v = *(const float2*)p; return f2pack(v.x, v.y);
}
__device__ __forceinline__ void f2st(float* p, u64 v) {      // aligned STS.64
    float lo, hi; f2unpack(v, lo, hi);
    *(float2*)p = make_float2(lo, hi);
}

template<int CSZ>
__global__ void __launch_bounds__(1024, 1) __cluster_dims__(CSZ, 1, 1)
wave_kernel(const float* __restrict__ xin,   // (NS, NT)
            const float* __restrict__ vp,    // (NZ, NX)
            const int*   __restrict__ src_z, // (NS,)
            const int*   __restrict__ src_x, // (NS,)
            const int*   __restrict__ rec_z, // (NS, NR)
            const int*   __restrict__ rec_x, // (NS, NR)
            float*       __restrict__ out)   // (NS, NT, NR, 1)
{
    constexpr int RPC  = NZ / CSZ;      // rows per CTA
    constexpr int RPT  = RPC / NG;      // rows per thread
    constexpr int ROWS = RPC + 2;       // + halo rows 0 and ROWS-1
    extern __shared__ float smem[];     // [2][ROWS][S]
    __shared__ __align__(8) uint64_t mbars[4];  // [0/1]=top par, [2/3]=bot par
    __shared__ int   rcnt;
    __shared__ int   rpos[NR];
    __shared__ short rid[NR];

    const int tid = threadIdx.x;
    const int g   = tid >> 7;           // row group
    const int tx  = tid & 127;          // column-pair index
    const int xi  = 2 + 2 * tx;         // first element col of pair
    const int s   = blockIdx.x / CSZ;   // shot
    uint32_t rank;
    asm("mov.u32 %0, %%cluster_ctarank;" : "=r"(rank));
    const int r0  = (int)rank * RPC;
    const int gz0 = g * RPT;

    for (int i = tid; i < 2 * ROWS * S; i += 1024) smem[i] = 0.0f;
    if (tid == 0) {
        rcnt = 0;
        for (int i = 0; i < 4; i++) mbar_init(smem_u32(&mbars[i]), 1);
    }
    __syncthreads();
    cluster_sync_();                    // mbars initialized cluster-wide

    if (tid < NR) {
        int rz = rec_z[s * NR + tid];
        if (rz >= r0 && rz < r0 + RPC) {
            int i = atomicAdd(&rcnt, 1);
            rpos[i] = (rz - r0 + 1) * S + rec_x[s * NR + tid] + 2;
            rid[i]  = (short)tid;
        }
    }

    const int  srcz    = src_z[s];
    const int  srcx    = src_x[s];
    const int  szc     = srcz - r0;
    const bool my_src  = (szc >= gz0 && szc < gz0 + RPT) && (tx == (srcx >> 1));
    const int  szl     = szc - gz0;
    const int  srclane = srcx & 1;

    u64 c2p[RPT], ccp[RPT], nco[RPT];
#pragma unroll
    for (int z = 0; z < RPT; z++) {
        float a0 = vp[(r0 + gz0 + z) * NX + 2 * tx]     * 0.001f;
        float a1 = vp[(r0 + gz0 + z) * NX + 2 * tx + 1] * 0.001f;
        c2p[z] = f2pack((a0 * a0) * 0.01f, (a1 * a1) * 0.01f);
        ccp[z] = 0ull;
        nco[z] = 0ull;                  // -p_{t-1}
    }
    __syncthreads();                    // rcnt/rpos/rid final

    // hoist receiver bookkeeping into registers
    const bool has_rec = (tid < rcnt);
    const int  myrpos  = has_rec ? rpos[tid] : 0;
    float*     outp    = out + (size_t)s * NT * NR + (has_rec ? (int)rid[tid] : 0);

    float* const b0 = smem;
    float* const b1 = smem + ROWS * S;
    const uint32_t base0 = smem_u32(b0);
    const uint32_t base1 = smem_u32(b1);
    const uint32_t mb_top[2] = { smem_u32(&mbars[0]), smem_u32(&mbars[1]) };
    const uint32_t mb_bot[2] = { smem_u32(&mbars[2]), smem_u32(&mbars[3]) };
    const bool has_up = (rank > 0);
    const bool has_dn = (rank < CSZ - 1);
    const bool gtop   = (g == 0);
    const bool gbot   = (g == NG - 1);

    const u64 NEG4 = f2pack(-4.0f, -4.0f);
    const u64 TWO  = f2pack( 2.0f,  2.0f);
    const u64 NEG1 = f2pack(-1.0f, -1.0f);

    const int off0  = (gz0 + 1) * S + xi;
    const int offSB = gz0 * S + xi;
    const int offSA = (gz0 + RPT + 1) * S + xi;

#define STEP_ROW(PN, z, below, above, oldcc, val)                              \
    {                                                                          \
        u64 cc = ccp[z];                                                       \
        float clo, chi; f2unpack(cc, clo, chi);                                \
        u64 vert = f2add(below, above);                                        \
        u64 horz = f2add(f2pack(lv[z], clo), f2pack(chi, rv[z]));              \
        u64 sum  = f2add(vert, horz);                                          \
        u64 lap  = f2fma(cc, NEG4, sum);                                       \
        u64 tmp  = f2fma(cc, TWO, nco[z]);                                     \
        val = f2fma(c2p[z], lap, tmp);                                         \
        nco[z] = f2mul(cc, NEG1);                                              \
        if (my_src && (z) == szl) {                                            \
            float a, b; f2unpack(val, a, b);                                   \
            if (srclane) b += srcval; else a += srcval;                        \
            val = f2pack(a, b);                                                \
        }                                                                      \
        ccp[z] = val;                                                          \
        f2st((PN) + off0 + (z) * S, val);                                      \
        oldcc = cc;                                                            \
    }

// One full phase, BOUNDARY-FIRST: wait -> boundary row -> push -> interior.
#define DO_STEP(PCUR, PNXT, RBASE, PAR, T, WAITOK, WPAR, OUTOFF)               \
    {                                                                          \
        if (tid == 0) {                                                        \
            if (has_up) mbar_expect(mb_top[PAR], NX * 4);                      \
            if (has_dn) mbar_expect(mb_bot[PAR], NX * 4);                      \
        }                                                                      \
        float srcval = 0.0f;                                                   \
        if (my_src) srcval = (__ldg(&xin[s * NT + (T)]) * 0.001f) * 0.001f;    \
        float lv[RPT], rv[RPT];                                                \
        _Pragma("unroll")                                                      \
        for (int z = 0; z < RPT; z++) {                                        \
            float2 a = *(const float2*)((PCUR) + off0 + z * S - 2);            \
            float2 b = *(const float2*)((PCUR) + off0 + z * S + 2);            \
            lv[z] = a.y; rv[z] = b.x;                                          \
        }                                                                      \
        u64 oldcc, val;                                                        \
        if (gtop) {                                                            \
            const u64 seamA = f2ld((PCUR) + offSA);                            \
            const u64 save0 = ccp[0];                                          \
            const u64 save1 = ccp[1];                                          \
            if (has_up && (WAITOK)) mbar_wait(mb_top[(PAR) ^ 1], (WPAR));      \
            {   /* boundary row 0 first, push immediately */                   \
                const u64 haloB = f2ld((PCUR) + offSB);                        \
                STEP_ROW(PNXT, 0, haloB, save1, oldcc, val);                   \
                if (has_up) {                                                  \
                    uint32_t rs = mapa32((RBASE) +                             \
                        (uint32_t)((ROWS - 1) * S + xi) * 4u, rank - 1);       \
                    uint32_t rm = mapa32(mb_bot[PAR], rank - 1);               \
                    st_async_f2(rs, rm, val);                                  \
                }                                                              \
            }                                                                  \
            u64 below = save0;                                                 \
            _Pragma("unroll")                                                  \
            for (int z = 1; z < RPT; z++) {                                    \
                u64 above = (z == RPT - 1) ? seamA : ccp[z + 1];               \
                STEP_ROW(PNXT, z, below, above, oldcc, val);                   \
                below = oldcc;                                                 \
            }                                                                  \
        } else if (gbot) {                                                     \
            const u64 seamB = f2ld((PCUR) + offSB);                            \
            const u64 saveL = ccp[RPT - 1];                                    \
            u64 belowB = ccp[RPT - 2];                                         \
            if (has_dn && (WAITOK)) mbar_wait(mb_bot[(PAR) ^ 1], (WPAR));      \
            {   /* boundary row RPT-1 first, push immediately */               \
                const u64 haloA = f2ld((PCUR) + offSA);                        \
                STEP_ROW(PNXT, RPT - 1, belowB, haloA, oldcc, val);            \
                if (has_dn) {                                                  \
                    uint32_t rs = mapa32((RBASE) + (uint32_t)(xi) * 4u,        \
                                         rank + 1);                            \
                    uint32_t rm = mapa32(mb_top[PAR], rank + 1);               \
                    st_async_f2(rs, rm, val);                                  \
                }                                                              \
            }                                                                  \
            u64 below = seamB;                                                 \
            _Pragma("unroll")                                                  \
            for (int z = 0; z < RPT - 1; z++) {                                \
                u64 above = (z == RPT - 2) ? saveL : ccp[z + 1];               \
                STEP_ROW(PNXT, z, below, above, oldcc, val);                   \
                below = oldcc;                                                 \
            }                                                                  \
        } else {                                                               \
            const u64 seamA = f2ld((PCUR) + offSA);                            \
            u64 below = f2ld((PCUR) + offSB);                                  \
            _Pragma("unroll")                                                  \
            for (int z = 0; z < RPT; z++) {                                    \
                u64 above = (z == RPT - 1) ? seamA : ccp[z + 1];               \
                STEP_ROW(PNXT, z, below, above, oldcc, val);                   \
                below = oldcc;                                                 \
            }                                                                  \
        }                                                                      \
        __syncthreads();                                                       \
        if (has_rec) outp[OUTOFF] = (PNXT)[myrpos];                            \
    }

    for (int t = 0; t < NT; t += 2) {
        const uint32_t m = (uint32_t)(t >> 1);
        // step A: t even, par=0, pcur=b0 -> pnxt=b1
        DO_STEP(b0, b1, base1, 0, t, t > 0, (m - 1) & 1, 0);
        // step B: t+1 odd, par=1, pcur=b1 -> pnxt=b0
        DO_STEP(b1, b0, base0, 1, t + 1, true, m & 1, NR);
        outp += 2 * NR;
    }

    // drain final phase so no st.async targets our smem after exit
    if (tid == 0) {
        const uint32_t fp = (NT - 1) & 1, fpar = ((NT - 1) >> 1) & 1;
        if (has_up) mbar_wait(mb_top[fp], fpar);
        if (has_dn) mbar_wait(mb_bot[fp], fpar);
    }
    __syncthreads();
    cluster_sync_();
#undef DO_STEP
#undef STEP_ROW
}

template<int CSZ>
static void launch_variant(const float* x, const float* vp, const int* sz,
                           const int* sx, const int* rz, const int* rx, float* out)
{
    const int smemb = 2 * (NZ / CSZ + 2) * S * (int)sizeof(float);
    cudaFuncSetAttribute(wave_kernel<CSZ>,
                         cudaFuncAttributeMaxDynamicSharedMemorySize, smemb);
    wave_kernel<CSZ><<<NS * CSZ, 1024, smemb>>>(x, vp, sz, sx, rz, rx, out);
}

extern "C" void kernel_launch(void* const* d_in, const int* in_sizes, int n_in,
                              void* d_out, int out_size)
{
    const float* x     = (const float*)d_in[0];
    const float* vp    = (const float*)d_in[1];
    const int*   src_z = (const int*)d_in[2];
    const int*   src_x = (const int*)d_in[3];
    const int*   rec_z = (const int*)d_in[4];
    const int*   rec_x = (const int*)d_in[5];
    float*       out   = (float*)d_out;

    const int smem16 = 2 * (NZ / 16 + 2) * S * (int)sizeof(float);
    bool use16 = false;
    if (cudaFuncSetAttribute(wave_kernel<16>,
            cudaFuncAttributeNonPortableClusterSizeAllowed, 1) == cudaSuccess &&
        cudaFuncSetAttribute(wave_kernel<16>,
            cudaFuncAttributeMaxDynamicSharedMemorySize, smem16) == cudaSuccess) {
        cudaLaunchConfig_t cfg = {};
        cfg.gridDim  = dim3(NS * 16, 1, 1);
        cfg.blockDim = dim3(1024, 1, 1);
        cfg.dynamicSmemBytes = (size_t)smem16;
        cudaLaunchAttribute attr[1];
        attr[0].id = cudaLaunchAttributeClusterDimension;
        attr[0].val.clusterDim = {16, 1, 1};
        cfg.attrs = attr;
        cfg.numAttrs = 1;
        int ncl = 0;
        if (cudaOccupancyMaxActiveClusters(&ncl, wave_kernel<16>, &cfg) == cudaSuccess
            && ncl >= NS) use16 = true;
        else cudaGetLastError();
    } else {
        cudaGetLastError();
    }

    if (use16) launch_variant<16>(x, vp, src_z, src_x, rec_z, rec_x, out);
    else       launch_variant<8>(x, vp, src_z, src_x, rec_z, rec_x, out);
}